// round 10
// baseline (speedup 1.0000x reference)
#include <cuda_runtime.h>

// Fused 1-level DWT (analysis lowpass, stride 2, symmetric pad) + synthesis
// lowpass (transposed conv, dilation 2). 64 rows of length 524288.
//
//   cA[m]    = sum_i H[i] * sig_mir(2m + i - 8)
//   ya[2u]   = sum_r H[8-2r] * cA[u+r]
//   ya[2u+1] = sum_r H[9-2r] * cA[u+r]
// mirror: q<0 -> -1-q ; q>=L -> 2L-1-q.
//
// R9: R8's 256-bit dense access pattern, two tiles per thread. 6 independent
// front-batched LDG.256 (6KB in flight per thread) + 2 dense STG.256. Tests
// whether R8 was latency-limited (expect ~35us) or at the HBM ceiling
// (expect flat ~39us).

#define TILE      2048
#define THREADS   256
#define PER_THR   8
#define BLKSPAN   (2 * TILE)    // outputs per block (two tiles)

__device__ __forceinline__ void ldg256(const float* __restrict__ p, float v[8])
{
    asm volatile("ld.global.nc.v8.f32 {%0,%1,%2,%3,%4,%5,%6,%7}, [%8];"
                 : "=f"(v[0]), "=f"(v[1]), "=f"(v[2]), "=f"(v[3]),
                   "=f"(v[4]), "=f"(v[5]), "=f"(v[6]), "=f"(v[7])
                 : "l"(p));
}

__device__ __forceinline__ void stg256(float* p, const float v[8])
{
    asm volatile("st.global.v8.f32 [%0], {%1,%2,%3,%4,%5,%6,%7,%8};"
                 :: "l"(p),
                    "f"(v[0]), "f"(v[1]), "f"(v[2]), "f"(v[3]),
                    "f"(v[4]), "f"(v[5]), "f"(v[6]), "f"(v[7])
                 : "memory");
}

__device__ __forceinline__ void load_mirror24(const float* __restrict__ xr,
                                              int t0, int L, float xv[24])
{
    #pragma unroll
    for (int i = 0; i < 24; i++) {
        int q = t0 - 8 + i;
        if (q < 0)        q = -1 - q;
        else if (q >= L)  q = 2 * L - 1 - q;
        xv[i] = xr[q];
    }
}

__device__ __forceinline__ void compute8(const float xv[24], float o[8])
{
    constexpr float H[10] = {
        0.160102397974125f,     0.6038292697974729f,
        0.7243085284385744f,    0.13842814590110342f,
       -0.24229488706619015f,  -0.03224486958502952f,
        0.07757149384006515f,  -0.006241490213011705f,
       -0.012580751999015526f,  0.003335725285001549f
    };

    float cA[8];
    #pragma unroll
    for (int r = 0; r < 8; r++) {
        float a = 0.0f;
        #pragma unroll
        for (int i = 0; i < 10; i++) {
            a = fmaf(H[i], xv[2*r + i], a);
        }
        cA[r] = a;
    }

    #pragma unroll
    for (int s = 0; s < 4; s++) {
        float e = 0.0f, od = 0.0f;
        #pragma unroll
        for (int rp = 0; rp < 5; rp++) {
            e  = fmaf(H[8 - 2*rp], cA[s + rp], e);
            od = fmaf(H[9 - 2*rp], cA[s + rp], od);
        }
        o[2*s + 0] = e;
        o[2*s + 1] = od;
    }
}

__global__ __launch_bounds__(THREADS)
void wavelet_v8x2_kernel(const float* __restrict__ x,
                         float* __restrict__ y,
                         int L, int blocksPerRow)
{
    const int blk = blockIdx.x;
    const int row = blockIdx.y;
    const long long rowbase = (long long)row * (long long)L;
    const float* xr = x + rowbase;

    const int t0 = blk * BLKSPAN + threadIdx.x * PER_THR;
    const int t1 = t0 + TILE;

    float xvA[24], xvB[24];

    if (blk == 0 || blk == blocksPerRow - 1) {
        // boundary blocks (128 of 8192): scalar mirrored loads
        load_mirror24(xr, t0, L, xvA);
        load_mirror24(xr, t1, L, xvB);
    } else {
        // interior: 6 independent dense LDG.256, front-batched
        ldg256(xr + t0 - 8, xvA + 0);
        ldg256(xr + t0,     xvA + 8);
        ldg256(xr + t0 + 8, xvA + 16);
        ldg256(xr + t1 - 8, xvB + 0);
        ldg256(xr + t1,     xvB + 8);
        ldg256(xr + t1 + 8, xvB + 16);
    }

    float oA[8], oB[8];
    compute8(xvA, oA);
    compute8(xvB, oB);

    stg256(y + rowbase + t0, oA);
    stg256(y + rowbase + t1, oB);
}

extern "C" void kernel_launch(void* const* d_in, const int* in_sizes, int n_in,
                              void* d_out, int out_size)
{
    const float* x = (const float*)d_in[0];
    float* y = (float*)d_out;

    const int B = 64;
    const int total = in_sizes[0];            // 64 * 128 * 4096
    const int L = total / B;                  // 524288
    const int blocksPerRow = L / BLKSPAN;     // 128

    dim3 grid(blocksPerRow, B);
    wavelet_v8x2_kernel<<<grid, THREADS>>>(x, y, L, blocksPerRow);
}

// round 11
// speedup vs baseline: 1.0050x; 1.0050x over previous
#include <cuda_runtime.h>

// Fused 1-level DWT (analysis lowpass, stride 2, symmetric pad) + synthesis
// lowpass (transposed conv, dilation 2). 64 rows of length 524288.
//
//   cA[m]    = sum_i H[i] * sig_mir(2m + i - 8)
//   ya[2u]   = sum_r H[8-2r] * cA[u+r]
//   ya[2u+1] = sum_r H[9-2r] * cA[u+r]
// mirror: q<0 -> -1-q ; q>=L -> 2L-1-q.
//
// R10: R8 structure (8 outputs/thread, 3 dense LDG.256 + 1 dense STG.256,
// fully dense 1024B warp transactions) + streaming cache hints:
// loads L2::evict_first, stores .cs. Data is touch-once in both directions;
// R8 already runs at ~87% of HBM spec (6.93 TB/s), this targets the residual.

#define TILE      2048
#define THREADS   256
#define PER_THR   8

__device__ __forceinline__ void ldg256_stream(const float* __restrict__ p, float v[8])
{
    asm volatile("ld.global.nc.L2::evict_first.v8.f32 {%0,%1,%2,%3,%4,%5,%6,%7}, [%8];"
                 : "=f"(v[0]), "=f"(v[1]), "=f"(v[2]), "=f"(v[3]),
                   "=f"(v[4]), "=f"(v[5]), "=f"(v[6]), "=f"(v[7])
                 : "l"(p));
}

__device__ __forceinline__ void stg256_stream(float* p, const float v[8])
{
    asm volatile("st.global.cs.v8.f32 [%0], {%1,%2,%3,%4,%5,%6,%7,%8};"
                 :: "l"(p),
                    "f"(v[0]), "f"(v[1]), "f"(v[2]), "f"(v[3]),
                    "f"(v[4]), "f"(v[5]), "f"(v[6]), "f"(v[7])
                 : "memory");
}

__global__ __launch_bounds__(THREADS)
void wavelet_v8s_kernel(const float* __restrict__ x,
                        float* __restrict__ y,
                        int L, int tilesPerRow)
{
    const int tile = blockIdx.x;
    const int row  = blockIdx.y;
    const long long rowbase = (long long)row * (long long)L;
    const float* xr = x + rowbase;

    const int t0 = tile * TILE + threadIdx.x * PER_THR;  // first output index

    float xv[24];  // sig[t0-8 .. t0+15]

    if (tile == 0 || tile == tilesPerRow - 1) {
        // boundary tiles (128 of 16384 blocks): scalar mirrored loads
        #pragma unroll
        for (int i = 0; i < 24; i++) {
            int q = t0 - 8 + i;
            if (q < 0)        q = -1 - q;
            else if (q >= L)  q = 2 * L - 1 - q;
            xv[i] = xr[q];
        }
    } else {
        // interior: 3 independent dense 256-bit loads (32B-aligned)
        ldg256_stream(xr + t0 - 8, xv + 0);
        ldg256_stream(xr + t0,     xv + 8);
        ldg256_stream(xr + t0 + 8, xv + 16);
    }

    constexpr float H[10] = {
        0.160102397974125f,     0.6038292697974729f,
        0.7243085284385744f,    0.13842814590110342f,
       -0.24229488706619015f,  -0.03224486958502952f,
        0.07757149384006515f,  -0.006241490213011705f,
       -0.012580751999015526f,  0.003335725285001549f
    };

    // stage 1: 8 approximation coefficients
    float cA[8];
    #pragma unroll
    for (int r = 0; r < 8; r++) {
        float a = 0.0f;
        #pragma unroll
        for (int i = 0; i < 10; i++) {
            a = fmaf(H[i], xv[2*r + i], a);
        }
        cA[r] = a;
    }

    // stage 2: 8 outputs (4 even/odd pairs)
    float o[8];
    #pragma unroll
    for (int s = 0; s < 4; s++) {
        float e = 0.0f, od = 0.0f;
        #pragma unroll
        for (int rp = 0; rp < 5; rp++) {
            e  = fmaf(H[8 - 2*rp], cA[s + rp], e);
            od = fmaf(H[9 - 2*rp], cA[s + rp], od);
        }
        o[2*s + 0] = e;
        o[2*s + 1] = od;
    }

    // one dense 256-bit streaming store (32B-aligned)
    stg256_stream(y + rowbase + t0, o);
}

extern "C" void kernel_launch(void* const* d_in, const int* in_sizes, int n_in,
                              void* d_out, int out_size)
{
    const float* x = (const float*)d_in[0];
    float* y = (float*)d_out;

    const int B = 64;
    const int total = in_sizes[0];          // 64 * 128 * 4096
    const int L = total / B;                // 524288
    const int tilesPerRow = L / TILE;       // 256

    dim3 grid(tilesPerRow, B);
    wavelet_v8s_kernel<<<grid, THREADS>>>(x, y, L, tilesPerRow);
}